// round 6
// baseline (speedup 1.0000x reference)
#include <cuda_runtime.h>
#include <cstdint>

#define IN_F   8192
#define OUT_F  8192
#define THR    50.0f
#define NT     256
#define NV     (IN_F / 4)         // 2048 float4 per row
#define FPT    (NV / NT)          // 8 float4 per thread per row

// ── Kernel A: spikes + v_new — 2 rows per block, 16-deep burst, 4 acc chains ──
__global__ __launch_bounds__(NT)
void snn_spike2_kernel(const float* __restrict__ x,
                       const float* __restrict__ syn,
                       const float* __restrict__ mp,
                       const float* __restrict__ thr,
                       float* __restrict__ out) {
    __shared__ float red[2][NT / 32];
    const int t  = threadIdx.x;
    const int r0 = blockIdx.x * 2;
    const int r1 = r0 + 1;

    const float4* sa4 = reinterpret_cast<const float4*>(syn + (size_t)r0 * IN_F);
    const float4* sb4 = reinterpret_cast<const float4*>(syn + (size_t)r1 * IN_F);
    const float4* x4  = reinterpret_cast<const float4*>(x);

    // 16 front-batched LDG.128 per thread — both rows fully in flight
    float4 sa[FPT], sb[FPT];
    #pragma unroll
    for (int j = 0; j < FPT; j++) sa[j] = __ldcs(&sa4[t + j * NT]);
    #pragma unroll
    for (int j = 0; j < FPT; j++) sb[j] = __ldcs(&sb4[t + j * NT]);

    // 4 independent accumulator chains (2 per row)
    float a0 = 0.0f, a1 = 0.0f, b0 = 0.0f, b1 = 0.0f;
    #pragma unroll
    for (int j = 0; j < FPT; j++) {
        float4 xv = __ldg(&x4[t + j * NT]);          // L1-resident 32 KB
        a0 += (sa[j].x > THR ? xv.x : 0.0f) + (sa[j].y > THR ? xv.y : 0.0f);
        a1 += (sa[j].z > THR ? xv.z : 0.0f) + (sa[j].w > THR ? xv.w : 0.0f);
        b0 += (sb[j].x > THR ? xv.x : 0.0f) + (sb[j].y > THR ? xv.y : 0.0f);
        b1 += (sb[j].z > THR ? xv.z : 0.0f) + (sb[j].w > THR ? xv.w : 0.0f);
    }
    float a = a0 + a1;
    float b = b0 + b1;
    #pragma unroll
    for (int off = 16; off > 0; off >>= 1) {
        a += __shfl_down_sync(0xffffffffu, a, off);
        b += __shfl_down_sync(0xffffffffu, b, off);
    }
    if ((t & 31) == 0) {
        red[0][t >> 5] = a;
        red[1][t >> 5] = b;
    }
    __syncthreads();

    if (t < 2) {                                      // parallel finalize
        const int r = (t == 0) ? r0 : r1;
        float cur = 0.0f;
        #pragma unroll
        for (int w = 0; w < NT / 32; w++) cur += red[t][w];
        float v  = __ldg(mp + r) * 0.6f + cur;
        float sp = (v >= __ldg(thr + r)) ? 1.0f : 0.0f;
        out[r] = sp;                                  // spikes
        out[OUT_F + r] = v * (1.0f - sp) * 0.3f;      // v_new
    }
}

// ── Kernel B: trace update (unchanged — measured 80.6% DRAM) ──
__global__ __launch_bounds__(NT)
void snn_trace_kernel(const float* __restrict__ x,
                      const float* __restrict__ elig,
                      const float* __restrict__ spikes,  // = out[0..OUT_F)
                      float* __restrict__ trace) {       // = out + 2*OUT_F
    const int o = blockIdx.x;
    const int t = threadIdx.x;

    const float sp = __ldg(&spikes[o]);

    const float4* e4 = reinterpret_cast<const float4*>(elig + (size_t)o * IN_F);
    const float4* x4 = reinterpret_cast<const float4*>(x);
    float4* o4 = reinterpret_cast<float4*>(trace + (size_t)o * IN_F);

    float4 e[FPT];
    #pragma unroll
    for (int j = 0; j < FPT; j++)
        e[j] = __ldcs(&e4[t + j * NT]);

    #pragma unroll
    for (int j = 0; j < FPT; j++) {
        float4 xv = __ldg(&x4[t + j * NT]);
        float4 r;
        r.x = fminf(fmaxf(fmaf(e[j].x, 0.7f, sp * xv.x), 0.0f), 3.0f);
        r.y = fminf(fmaxf(fmaf(e[j].y, 0.7f, sp * xv.y), 0.0f), 3.0f);
        r.z = fminf(fmaxf(fmaf(e[j].z, 0.7f, sp * xv.z), 0.0f), 3.0f);
        r.w = fminf(fmaxf(fmaf(e[j].w, 0.7f, sp * xv.w), 0.0f), 3.0f);
        __stcs(&o4[t + j * NT], r);
    }
}

extern "C" void kernel_launch(void* const* d_in, const int* in_sizes, int n_in,
                              void* d_out, int out_size) {
    const float* x    = (const float*)d_in[0];  // spike_input [1, 8192]
    const float* syn  = (const float*)d_in[1];  // synapse_states [8192, 8192]
    const float* mp   = (const float*)d_in[2];  // membrane_potential [8192]
    const float* thr  = (const float*)d_in[3];  // adaptive_threshold [8192]
    const float* elig = (const float*)d_in[4];  // eligibility_trace [8192, 8192]
    float* out = (float*)d_out;                 // [spikes | v_new | trace_new]

    snn_spike2_kernel<<<OUT_F / 2, NT>>>(x, syn, mp, thr, out);
    snn_trace_kernel<<<OUT_F, NT>>>(x, elig, out, out + 2 * (size_t)OUT_F);
}

// round 7
// speedup vs baseline: 1.0997x; 1.0997x over previous
#include <cuda_runtime.h>
#include <cstdint>

#define IN_F   8192
#define OUT_F  8192
#define THR    50.0f
#define NT     256
#define NV     (IN_F / 4)         // 2048 float4 per row
#define FPT    (NV / NT)          // 8 float4 per thread — one burst = full row

__global__ __launch_bounds__(NT)
void snn_fused2_kernel(const float* __restrict__ x,
                       const float* __restrict__ syn,
                       const float* __restrict__ mp,
                       const float* __restrict__ thr,
                       const float* __restrict__ elig,
                       float* __restrict__ out) {
    __shared__ float red[NT / 32];
    const int o = blockIdx.x;
    const int t = threadIdx.x;

    const float4* x4 = reinterpret_cast<const float4*>(x);   // 32 KB, L1-resident across CTAs
    const float4* s4 = reinterpret_cast<const float4*>(syn + (size_t)o * IN_F);

    // ── Phase 1: front-batched full-row burst of syn ──
    float4 s[FPT];
    #pragma unroll
    for (int j = 0; j < FPT; j++)
        s[j] = __ldcs(&s4[t + j * NT]);          // 8 LDG.128 in flight

    float a0 = 0.0f, a1 = 0.0f, a2 = 0.0f, a3 = 0.0f;   // 4 independent chains
    #pragma unroll
    for (int j = 0; j < FPT; j++) {
        float4 xv = __ldg(&x4[t + j * NT]);      // L1 hit after warm-up
        a0 += (s[j].x > THR ? xv.x : 0.0f);
        a1 += (s[j].y > THR ? xv.y : 0.0f);
        a2 += (s[j].z > THR ? xv.z : 0.0f);
        a3 += (s[j].w > THR ? xv.w : 0.0f);
    }
    float acc = (a0 + a1) + (a2 + a3);
    #pragma unroll
    for (int off = 16; off > 0; off >>= 1)
        acc += __shfl_down_sync(0xffffffffu, acc, off);
    if ((t & 31) == 0) red[t >> 5] = acc;
    __syncthreads();                             // the only barrier

    // Redundant per-thread finalize (avoids a second barrier)
    float cur = 0.0f;
    #pragma unroll
    for (int w = 0; w < NT / 32; w++) cur += red[w];
    const float v  = __ldg(mp + o) * 0.6f + cur;
    const float sp = (v >= __ldg(thr + o)) ? 1.0f : 0.0f;
    if (t == 0) {
        out[o] = sp;                             // spikes
        out[OUT_F + o] = v * (1.0f - sp) * 0.3f; // v_new
    }

    // ── Phase 2: trace_new = clip(elig*0.7 + sp*x, 0, 3) ──
    const float4* e4 = reinterpret_cast<const float4*>(elig + (size_t)o * IN_F);
    float4* o4 = reinterpret_cast<float4*>(out + 2 * (size_t)OUT_F
                                               + (size_t)o * IN_F);
    float4 e[FPT];
    #pragma unroll
    for (int j = 0; j < FPT; j++)
        e[j] = __ldcs(&e4[t + j * NT]);          // 8 LDG.128 in flight

    #pragma unroll
    for (int j = 0; j < FPT; j++) {
        float4 xv = __ldg(&x4[t + j * NT]);      // L1 hit
        float4 r;
        r.x = fminf(fmaxf(fmaf(e[j].x, 0.7f, sp * xv.x), 0.0f), 3.0f);
        r.y = fminf(fmaxf(fmaf(e[j].y, 0.7f, sp * xv.y), 0.0f), 3.0f);
        r.z = fminf(fmaxf(fmaf(e[j].z, 0.7f, sp * xv.z), 0.0f), 3.0f);
        r.w = fminf(fmaxf(fmaf(e[j].w, 0.7f, sp * xv.w), 0.0f), 3.0f);
        __stcs(&o4[t + j * NT], r);              // streaming store
    }
}

extern "C" void kernel_launch(void* const* d_in, const int* in_sizes, int n_in,
                              void* d_out, int out_size) {
    const float* x    = (const float*)d_in[0];  // spike_input [1, 8192]
    const float* syn  = (const float*)d_in[1];  // synapse_states [8192, 8192]
    const float* mp   = (const float*)d_in[2];  // membrane_potential [8192]
    const float* thr  = (const float*)d_in[3];  // adaptive_threshold [8192]
    const float* elig = (const float*)d_in[4];  // eligibility_trace [8192, 8192]
    float* out = (float*)d_out;                 // [spikes | v_new | trace_new]

    snn_fused2_kernel<<<OUT_F, NT>>>(x, syn, mp, thr, elig, out);
}

// round 8
// speedup vs baseline: 1.1021x; 1.0022x over previous
#include <cuda_runtime.h>
#include <cstdint>

#define IN_F   8192
#define OUT_F  8192
#define THR    50.0f
#define NT     256
#define NV     (IN_F / 4)         // 2048 float4 per row
#define FPT    (NV / NT)          // 8 float4 per thread — one burst = full row

__global__ __launch_bounds__(NT)
void snn_fused3_kernel(const float* __restrict__ x,
                       const float* __restrict__ syn,
                       const float* __restrict__ mp,
                       const float* __restrict__ thr,
                       const float* __restrict__ elig,
                       float* __restrict__ out) {
    __shared__ float red[NT / 32];
    const int o = blockIdx.x;
    const int t = threadIdx.x;

    const float4* x4 = reinterpret_cast<const float4*>(x);   // 32 KB, L1-resident
    const float4* s4 = reinterpret_cast<const float4*>(syn  + (size_t)o * IN_F);
    const float4* e4 = reinterpret_cast<const float4*>(elig + (size_t)o * IN_F);

    // ── Phase 1: front-batched full-row burst of syn ──
    float4 s[FPT];
    #pragma unroll
    for (int j = 0; j < FPT; j++)
        s[j] = __ldcs(&s4[t + j * NT]);          // 8 LDG.128 in flight

    float a0 = 0.0f, a1 = 0.0f, a2 = 0.0f, a3 = 0.0f;   // 4 independent chains
    #pragma unroll
    for (int j = 0; j < FPT; j++) {
        float4 xv = __ldg(&x4[t + j * NT]);      // L1 hit after warm-up
        a0 += (s[j].x > THR ? xv.x : 0.0f);
        a1 += (s[j].y > THR ? xv.y : 0.0f);
        a2 += (s[j].z > THR ? xv.z : 0.0f);
        a3 += (s[j].w > THR ? xv.w : 0.0f);
    }
    // s[] is dead here — issue the elig burst NOW so it flies during the
    // reduce/barrier/finalize (ptxas can reuse s[]'s registers for e[]).
    float4 e[FPT];
    #pragma unroll
    for (int j = 0; j < FPT; j++)
        e[j] = __ldcs(&e4[t + j * NT]);          // 8 LDG.128 in flight across barrier

    float acc = (a0 + a1) + (a2 + a3);
    #pragma unroll
    for (int off = 16; off > 0; off >>= 1)
        acc += __shfl_down_sync(0xffffffffu, acc, off);
    if ((t & 31) == 0) red[t >> 5] = acc;
    __syncthreads();                             // elig loads still in flight

    float cur = 0.0f;
    #pragma unroll
    for (int w = 0; w < NT / 32; w++) cur += red[w];
    const float v  = __ldg(mp + o) * 0.6f + cur;
    const float sp = (v >= __ldg(thr + o)) ? 1.0f : 0.0f;
    if (t == 0) {
        out[o] = sp;                             // spikes
        out[OUT_F + o] = v * (1.0f - sp) * 0.3f; // v_new
    }

    // ── Phase 2: consume elig burst → trace ──
    float4* o4 = reinterpret_cast<float4*>(out + 2 * (size_t)OUT_F
                                               + (size_t)o * IN_F);
    #pragma unroll
    for (int j = 0; j < FPT; j++) {
        float4 xv = __ldg(&x4[t + j * NT]);      // L1 hit
        float4 r;
        r.x = fminf(fmaxf(fmaf(e[j].x, 0.7f, sp * xv.x), 0.0f), 3.0f);
        r.y = fminf(fmaxf(fmaf(e[j].y, 0.7f, sp * xv.y), 0.0f), 3.0f);
        r.z = fminf(fmaxf(fmaf(e[j].z, 0.7f, sp * xv.z), 0.0f), 3.0f);
        r.w = fminf(fmaxf(fmaf(e[j].w, 0.7f, sp * xv.w), 0.0f), 3.0f);
        __stcs(&o4[t + j * NT], r);              // streaming store
    }
}

extern "C" void kernel_launch(void* const* d_in, const int* in_sizes, int n_in,
                              void* d_out, int out_size) {
    const float* x    = (const float*)d_in[0];  // spike_input [1, 8192]
    const float* syn  = (const float*)d_in[1];  // synapse_states [8192, 8192]
    const float* mp   = (const float*)d_in[2];  // membrane_potential [8192]
    const float* thr  = (const float*)d_in[3];  // adaptive_threshold [8192]
    const float* elig = (const float*)d_in[4];  // eligibility_trace [8192, 8192]
    float* out = (float*)d_out;                 // [spikes | v_new | trace_new]

    snn_fused3_kernel<<<OUT_F, NT>>>(x, syn, mp, thr, elig, out);
}

// round 9
// speedup vs baseline: 1.1057x; 1.0033x over previous
#include <cuda_runtime.h>
#include <cstdint>

#define IN_F   8192
#define OUT_F  8192
#define THR    50.0f
#define NT     256
#define NV     (IN_F / 4)         // 2048 float4 per row
#define FPT    (NV / NT)          // 8 float4 per thread — one burst = full row
#define HALF   (FPT / 2)          // 4: elig burst split across the barrier

__global__ __launch_bounds__(NT)
void snn_fused4_kernel(const float* __restrict__ x,
                       const float* __restrict__ syn,
                       const float* __restrict__ mp,
                       const float* __restrict__ thr,
                       const float* __restrict__ elig,
                       float* __restrict__ out) {
    __shared__ float red[NT / 32];
    const int o = blockIdx.x;
    const int t = threadIdx.x;

    const float4* x4 = reinterpret_cast<const float4*>(x);   // 32 KB, L1-resident
    const float4* s4 = reinterpret_cast<const float4*>(syn  + (size_t)o * IN_F);
    const float4* e4 = reinterpret_cast<const float4*>(elig + (size_t)o * IN_F);

    // ── Phase 1: front-batched full-row burst of syn ──
    float4 s[FPT];
    #pragma unroll
    for (int j = 0; j < FPT; j++)
        s[j] = __ldcs(&s4[t + j * NT]);          // 8 LDG.128 in flight

    float a0 = 0.0f, a1 = 0.0f, a2 = 0.0f, a3 = 0.0f;   // 4 independent chains
    #pragma unroll
    for (int j = 0; j < FPT; j++) {
        float4 xv = __ldg(&x4[t + j * NT]);      // L1 hit after warm-up
        a0 += (s[j].x > THR ? xv.x : 0.0f);
        a1 += (s[j].y > THR ? xv.y : 0.0f);
        a2 += (s[j].z > THR ? xv.z : 0.0f);
        a3 += (s[j].w > THR ? xv.w : 0.0f);
    }

    // First HALF of the elig burst — covers the reduce/barrier/finalize window
    // with only 16 live registers (vs 32 in R8).
    float4 e[HALF];
    #pragma unroll
    for (int j = 0; j < HALF; j++)
        e[j] = __ldcs(&e4[t + j * NT]);

    float acc = (a0 + a1) + (a2 + a3);
    #pragma unroll
    for (int off = 16; off > 0; off >>= 1)
        acc += __shfl_down_sync(0xffffffffu, acc, off);
    if ((t & 31) == 0) red[t >> 5] = acc;
    __syncthreads();                             // elig half-burst still in flight

    float cur = 0.0f;
    #pragma unroll
    for (int w = 0; w < NT / 32; w++) cur += red[w];
    const float v  = __ldg(mp + o) * 0.6f + cur;
    const float sp = (v >= __ldg(thr + o)) ? 1.0f : 0.0f;
    if (t == 0) {
        out[o] = sp;                             // spikes
        out[OUT_F + o] = v * (1.0f - sp) * 0.3f; // v_new
    }

    // ── Phase 2 ──
    float4* o4 = reinterpret_cast<float4*>(out + 2 * (size_t)OUT_F
                                               + (size_t)o * IN_F);

    // Second half burst — overlaps consumption/stores of the first half
    float4 e2[HALF];
    #pragma unroll
    for (int j = 0; j < HALF; j++)
        e2[j] = __ldcs(&e4[t + (HALF + j) * NT]);

    #pragma unroll
    for (int j = 0; j < HALF; j++) {
        float4 xv = __ldg(&x4[t + j * NT]);
        float4 r;
        r.x = fminf(fmaxf(fmaf(e[j].x, 0.7f, sp * xv.x), 0.0f), 3.0f);
        r.y = fminf(fmaxf(fmaf(e[j].y, 0.7f, sp * xv.y), 0.0f), 3.0f);
        r.z = fminf(fmaxf(fmaf(e[j].z, 0.7f, sp * xv.z), 0.0f), 3.0f);
        r.w = fminf(fmaxf(fmaf(e[j].w, 0.7f, sp * xv.w), 0.0f), 3.0f);
        __stcs(&o4[t + j * NT], r);
    }
    #pragma unroll
    for (int j = 0; j < HALF; j++) {
        float4 xv = __ldg(&x4[t + (HALF + j) * NT]);
        float4 r;
        r.x = fminf(fmaxf(fmaf(e2[j].x, 0.7f, sp * xv.x), 0.0f), 3.0f);
        r.y = fminf(fmaxf(fmaf(e2[j].y, 0.7f, sp * xv.y), 0.0f), 3.0f);
        r.z = fminf(fmaxf(fmaf(e2[j].z, 0.7f, sp * xv.z), 0.0f), 3.0f);
        r.w = fminf(fmaxf(fmaf(e2[j].w, 0.7f, sp * xv.w), 0.0f), 3.0f);
        __stcs(&o4[t + (HALF + j) * NT], r);
    }
}

extern "C" void kernel_launch(void* const* d_in, const int* in_sizes, int n_in,
                              void* d_out, int out_size) {
    const float* x    = (const float*)d_in[0];  // spike_input [1, 8192]
    const float* syn  = (const float*)d_in[1];  // synapse_states [8192, 8192]
    const float* mp   = (const float*)d_in[2];  // membrane_potential [8192]
    const float* thr  = (const float*)d_in[3];  // adaptive_threshold [8192]
    const float* elig = (const float*)d_in[4];  // eligibility_trace [8192, 8192]
    float* out = (float*)d_out;                 // [spikes | v_new | trace_new]

    snn_fused4_kernel<<<OUT_F, NT>>>(x, syn, mp, thr, elig, out);
}